// round 17
// baseline (speedup 1.0000x reference)
#include <cuda_runtime.h>
#include <math.h>
#include <stdint.h>

#define B_  32
#define N_  1024
#define D_  256
#define NEGMASK (-9.0e15f)
#define ALPHA_  0.2f

// ---------------- device scratch ----------------
__device__ float g_z [B_ * N_ * D_];     // z [b][j][d], tf32-RNA-rounded (32MB)
__device__ float g_p [B_ * N_ * N_];     // P [b][i][j], tf32 softmax probs (128MB)
__device__ float g_s1[B_ * N_];
__device__ float g_s2[B_ * N_];
__device__ float g_s1p[2][B_ * N_];
__device__ float g_s2p[2][B_ * N_];

// ---------------- helpers ----------------
__device__ __forceinline__ uint32_t smem_u32(const void* p) {
    uint32_t a;
    asm("{ .reg .u64 t; cvta.to.shared.u64 t, %1; cvt.u32.u64 %0, t; }" : "=r"(a) : "l"(p));
    return a;
}
__device__ __forceinline__ uint32_t tf32u(float f) {
    uint32_t u; asm("cvt.rna.tf32.f32 %0, %1;" : "=r"(u) : "f"(f));
    return u;
}
__device__ __forceinline__ float tf32f(float f) { return __uint_as_float(tf32u(f)); }

#define CP_ASYNC16(sm, gp) \
    asm volatile("cp.async.cg.shared.global [%0], [%1], 16;" :: "r"(sm), "l"(gp) : "memory")
#define CP_COMMIT()  asm volatile("cp.async.commit_group;" ::: "memory")
#define CP_WAIT0()   asm volatile("cp.async.wait_group 0;" ::: "memory")

__device__ __forceinline__ void mma_tf32(float* c, uint32_t a0, uint32_t a1,
                                         uint32_t a2, uint32_t a3,
                                         uint32_t b0, uint32_t b1) {
    asm volatile(
        "mma.sync.aligned.m16n8k8.row.col.f32.tf32.tf32.f32 "
        "{%0,%1,%2,%3}, {%4,%5,%6,%7}, {%8,%9}, {%0,%1,%2,%3};"
        : "+f"(c[0]), "+f"(c[1]), "+f"(c[2]), "+f"(c[3])
        : "r"(a0), "r"(a1), "r"(a2), "r"(a3), "r"(b0), "r"(b1));
}

// ---------------------------------------------------------------------------
// Kernel 1: z = tf32_rna( h @ W^T + b ) + fused s1/s2 partials.
// Double-buffered smem, ONE barrier per k-chunk. FIXED: 32 chunks (R16 bug
// ran only 8 -> K=64 of 256).
// ---------------------------------------------------------------------------
__global__ __launch_bounds__(256) void k_zgemm7(const float* __restrict__ h,
                                                const float* __restrict__ W,
                                                const float* __restrict__ bias,
                                                const float* __restrict__ av) {
    __shared__ float As[2][8][128];
    __shared__ float Bs[2][8][128];
    const int t  = threadIdx.x;
    const int bm = blockIdx.y;
    const int bn = blockIdx.x;
    const int tr = t >> 4, tc = t & 15;
    const int lm = t >> 1, lx = t & 1;

    const float* hA = h + (size_t)(bm * 128 + lm) * D_ + 4 * lx;
    const float* wB = W + (size_t)(bn * 128 + lm) * D_ + 4 * lx;

    float acc[8][8];
#pragma unroll
    for (int i = 0; i < 8; i++)
#pragma unroll
        for (int j = 0; j < 8; j++) acc[i][j] = 0.f;

    // prologue: chunk 0 -> buf 0 (STS), prefetch chunk 1 regs
    float4 avv = *(const float4*)(hA);
    float4 bvv = *(const float4*)(wB);
    As[0][4 * lx + 0][lm] = avv.x; As[0][4 * lx + 1][lm] = avv.y;
    As[0][4 * lx + 2][lm] = avv.z; As[0][4 * lx + 3][lm] = avv.w;
    Bs[0][4 * lx + 0][lm] = bvv.x; Bs[0][4 * lx + 1][lm] = bvv.y;
    Bs[0][4 * lx + 2][lm] = bvv.z; Bs[0][4 * lx + 3][lm] = bvv.w;
    avv = *(const float4*)(hA + 8);
    bvv = *(const float4*)(wB + 8);

    for (int kc = 0; kc < 32; kc++) {     // 32 chunks x 8 k = 256  [FIX]
        __syncthreads();   // sts(kc) visible; buf[(kc+1)&1] free (fma(kc-1) done)
        if (kc < 31) {
            const int nb = (kc + 1) & 1;
            As[nb][4 * lx + 0][lm] = avv.x; As[nb][4 * lx + 1][lm] = avv.y;
            As[nb][4 * lx + 2][lm] = avv.z; As[nb][4 * lx + 3][lm] = avv.w;
            Bs[nb][4 * lx + 0][lm] = bvv.x; Bs[nb][4 * lx + 1][lm] = bvv.y;
            Bs[nb][4 * lx + 2][lm] = bvv.z; Bs[nb][4 * lx + 3][lm] = bvv.w;
            if (kc < 30) {
                avv = *(const float4*)(hA + (kc + 2) * 8);
                bvv = *(const float4*)(wB + (kc + 2) * 8);
            }
        }
        const int cb = kc & 1;
#pragma unroll
        for (int k = 0; k < 8; k++) {
            float ra[8], rb[8];
            *(float4*)&ra[0] = *(const float4*)&As[cb][k][4 * tr];
            *(float4*)&ra[4] = *(const float4*)&As[cb][k][64 + 4 * tr];
            *(float4*)&rb[0] = *(const float4*)&Bs[cb][k][4 * tc];
            *(float4*)&rb[4] = *(const float4*)&Bs[cb][k][64 + 4 * tc];
#pragma unroll
            for (int i = 0; i < 8; i++)
#pragma unroll
                for (int j = 0; j < 8; j++) acc[i][j] += ra[i] * rb[j];
        }
    }

    // ---- epilogue: bias into acc, s1/s2 partials, tf32 store (proven R15)
    float bcol[8], a1c[8], a2c[8];
#pragma unroll
    for (int j = 0; j < 4; j++) {
        int c0 = bn * 128 + 4 * tc + j;
        int c1 = bn * 128 + 64 + 4 * tc + j;
        bcol[j]     = __ldg(bias + c0);    bcol[4 + j] = __ldg(bias + c1);
        a1c[j]      = __ldg(av + c0);      a1c[4 + j]  = __ldg(av + c1);
        a2c[j]      = __ldg(av + D_ + c0); a2c[4 + j]  = __ldg(av + D_ + c1);
    }
    float s1g[8], s2g[8];
#pragma unroll
    for (int i = 0; i < 8; i++) {
        float p1 = 0.f, p2 = 0.f;
#pragma unroll
        for (int j = 0; j < 8; j++) {
            acc[i][j] += bcol[j];
            p1 += acc[i][j] * a1c[j];
            p2 += acc[i][j] * a2c[j];
        }
        s1g[i] = p1; s2g[i] = p2;
    }
#pragma unroll
    for (int o = 1; o <= 8; o <<= 1) {
#pragma unroll
        for (int i = 0; i < 8; i++) {
            s1g[i] += __shfl_xor_sync(0xffffffffu, s1g[i], o);
            s2g[i] += __shfl_xor_sync(0xffffffffu, s2g[i], o);
        }
    }
    if (tc == 0) {
#pragma unroll
        for (int i = 0; i < 8; i++) {
            int r   = (i < 4) ? (4 * tr + i) : (64 + 4 * tr + (i - 4));
            int row = bm * 128 + r;
            g_s1p[bn][row] = s1g[i];
            g_s2p[bn][row] = s2g[i];
        }
    }
#pragma unroll
    for (int i = 0; i < 8; i++) {
        int r   = (i < 4) ? (4 * tr + i) : (64 + 4 * tr + (i - 4));
        int row = bm * 128 + r;
        float* zp = g_z + (size_t)row * D_ + bn * 128;
        float4 o0 = make_float4(tf32f(acc[i][0]), tf32f(acc[i][1]),
                                tf32f(acc[i][2]), tf32f(acc[i][3]));
        float4 o1 = make_float4(tf32f(acc[i][4]), tf32f(acc[i][5]),
                                tf32f(acc[i][6]), tf32f(acc[i][7]));
        *(float4*)(zp + 4 * tc)      = o0;
        *(float4*)(zp + 64 + 4 * tc) = o1;
    }
}

// ---------------------------------------------------------------------------
// Kernel 2: combine the two s1/s2 partials (proven)
// ---------------------------------------------------------------------------
__global__ __launch_bounds__(256) void k_combine2() {
    int id = blockIdx.x * 256 + threadIdx.x;
    g_s1[id] = g_s1p[0][id] + g_s1p[1][id];
    g_s2[id] = g_s2p[0][id] + g_s2p[1][id];
}

// ---------------------------------------------------------------------------
// Kernel 3: mask stats (proven passes 1-2) + pass 3: materialize P -> g_p
// ---------------------------------------------------------------------------
__global__ __launch_bounds__(256) void k_maskstat4(const int* __restrict__ adj) {
    __shared__ float s2s[N_];
    int row0 = blockIdx.x * 8;
    int b    = row0 >> 10;
    {
        const float4* s = (const float4*)(g_s2 + ((size_t)b << 10));
        ((float4*)s2s)[threadIdx.x] = s[threadIdx.x];
    }
    __syncthreads();
    int w = threadIdx.x >> 5, lane = threadIdx.x & 31;
    int row = row0 + w;
    float s1i = g_s1[row];
    const int4*   arow4 = (const int4*)(adj + (size_t)row * N_);
    const float4* s2s4  = (const float4*)s2s;

    // pass 1: masks + row max
    uint32_t nibs = 0;
    float m = -INFINITY;
#pragma unroll
    for (int q = 0; q < 8; q++) {
        int4   a = __ldg(arow4 + lane + 32 * q);
        float4 s = s2s4[lane + 32 * q];
        float x0 = s1i + s.x; x0 = (x0 >= 0.f) ? x0 : (ALPHA_ * x0);
        float x1 = s1i + s.y; x1 = (x1 >= 0.f) ? x1 : (ALPHA_ * x1);
        float x2 = s1i + s.z; x2 = (x2 >= 0.f) ? x2 : (ALPHA_ * x2);
        float x3 = s1i + s.w; x3 = (x3 >= 0.f) ? x3 : (ALPHA_ * x3);
        uint32_t nib = (a.x > 0 ? 1u : 0u) | (a.y > 0 ? 2u : 0u)
                     | (a.z > 0 ? 4u : 0u) | (a.w > 0 ? 8u : 0u);
        nibs |= nib << (4 * q);
        if (nib & 1u) m = fmaxf(m, x0);
        if (nib & 2u) m = fmaxf(m, x1);
        if (nib & 4u) m = fmaxf(m, x2);
        if (nib & 8u) m = fmaxf(m, x3);
    }
#pragma unroll
    for (int o = 16; o > 0; o >>= 1) m = fmaxf(m, __shfl_xor_sync(0xffffffffu, m, o));

    // pass 2: l
    float l = 0.f;
#pragma unroll
    for (int q = 0; q < 8; q++) {
        float4 s = s2s4[lane + 32 * q];
        uint32_t nib = (nibs >> (4 * q)) & 0xFu;
        float x0 = s1i + s.x; x0 = (x0 >= 0.f) ? x0 : (ALPHA_ * x0);
        float x1 = s1i + s.y; x1 = (x1 >= 0.f) ? x1 : (ALPHA_ * x1);
        float x2 = s1i + s.z; x2 = (x2 >= 0.f) ? x2 : (ALPHA_ * x2);
        float x3 = s1i + s.w; x3 = (x3 >= 0.f) ? x3 : (ALPHA_ * x3);
        if (nib & 1u) l += __expf(x0 - m);
        if (nib & 2u) l += __expf(x1 - m);
        if (nib & 4u) l += __expf(x2 - m);
        if (nib & 8u) l += __expf(x3 - m);
    }
#pragma unroll
    for (int o = 16; o > 0; o >>= 1) l += __shfl_xor_sync(0xffffffffu, l, o);
    float linv = 1.0f / l;

    // pass 3: write P row (tf32, 0 where disconnected), coalesced float4
    float* prow = g_p + (size_t)row * N_;
#pragma unroll
    for (int q = 0; q < 8; q++) {
        float4 s = s2s4[lane + 32 * q];
        uint32_t nib = (nibs >> (4 * q)) & 0xFu;
        float x0 = s1i + s.x; x0 = (x0 >= 0.f) ? x0 : (ALPHA_ * x0);
        float x1 = s1i + s.y; x1 = (x1 >= 0.f) ? x1 : (ALPHA_ * x1);
        float x2 = s1i + s.z; x2 = (x2 >= 0.f) ? x2 : (ALPHA_ * x2);
        float x3 = s1i + s.w; x3 = (x3 >= 0.f) ? x3 : (ALPHA_ * x3);
        float4 p;
        p.x = (nib & 1u) ? __uint_as_float(tf32u(__expf(x0 - m) * linv)) : 0.f;
        p.y = (nib & 2u) ? __uint_as_float(tf32u(__expf(x1 - m) * linv)) : 0.f;
        p.z = (nib & 4u) ? __uint_as_float(tf32u(__expf(x2 - m) * linv)) : 0.f;
        p.w = (nib & 8u) ? __uint_as_float(tf32u(__expf(x3 - m) * linv)) : 0.f;
        *(float4*)(prow + 4 * (lane + 32 * q)) = p;
    }
}

// ---------------------------------------------------------------------------
// Kernel 4: out = ELU( P @ Z ) -- PURE GEMM (P and Z cp.async double-buffered)
// smem floats: ZS0[32][264] ZS1 | PS0[64][36] PS1 = 21504 fl (86KB/CTA)
// ---------------------------------------------------------------------------
#define AT_ZS0 0
#define AT_ZS1 8448
#define AT_PS0 16896
#define AT_PS1 19200
#define AT_SMF 21504

__global__ __launch_bounds__(256, 2) void k_attn10(const float* __restrict__ pmat,
                                                   float* __restrict__ out) {
    extern __shared__ __align__(16) float sm[];
    const uint32_t sb = smem_u32(sm);
    const uint32_t* smu = (const uint32_t*)sm;

    const int t    = threadIdx.x;
    const int lane = t & 31;
    const int wid  = t >> 5;
    const int wr   = wid & 1;
    const int wc   = wid >> 1;
    const int g    = lane >> 2;
    const int tq   = lane & 3;

    const int b  = blockIdx.y;
    const int i0 = blockIdx.x * 64;

    const char* zbb = (const char*)(g_z + ((size_t)b << 18));
    const char* pbb = (const char*)(pmat + (((size_t)b << 10) + i0) * N_);

    float acc[2][8][4];
#pragma unroll
    for (int mt = 0; mt < 2; mt++)
#pragma unroll
        for (int nt = 0; nt < 8; nt++)
#pragma unroll
            for (int q = 0; q < 4; q++) acc[mt][nt][q] = 0.f;

    // prologue: Z(0) + P(0)
#pragma unroll
    for (int q = 0; q < 8; q++) {
        int idx = t + 256 * q, r = idx >> 6, s = idx & 63;
        CP_ASYNC16(sb + (AT_ZS0 + r * 264) * 4 + s * 16,
                   zbb + (size_t)r * 1024 + s * 16);
    }
#pragma unroll
    for (int q = 0; q < 2; q++) {
        int idx = t + 256 * q, r = idx >> 3, s = idx & 7;
        CP_ASYNC16(sb + (AT_PS0 + r * 36) * 4 + s * 16,
                   pbb + (size_t)r * 4096 + s * 16);
    }
    CP_COMMIT();

    for (int c = 0; c < 32; c++) {
        CP_WAIT0();
        __syncthreads();     // Z(c),P(c) visible to all; mma(c-1) complete
        if (c < 31) {        // prefetch Z(c+1)+P(c+1), overlapping mma(c)
            const uint32_t zoff = ((c + 1) & 1) ? AT_ZS1 : AT_ZS0;
            const uint32_t poff = ((c + 1) & 1) ? AT_PS1 : AT_PS0;
#pragma unroll
            for (int q = 0; q < 8; q++) {
                int idx = t + 256 * q, r = idx >> 6, s = idx & 63;
                CP_ASYNC16(sb + (zoff + r * 264) * 4 + s * 16,
                           zbb + (size_t)(32 * (c + 1) + r) * 1024 + s * 16);
            }
#pragma unroll
            for (int q = 0; q < 2; q++) {
                int idx = t + 256 * q, r = idx >> 3, s = idx & 7;
                CP_ASYNC16(sb + (poff + r * 36) * 4 + s * 16,
                           pbb + (size_t)r * 4096 + (size_t)(c + 1) * 128 + s * 16);
            }
            CP_COMMIT();
        }
        {
            const uint32_t zofs = (c & 1) ? AT_ZS1 : AT_ZS0;
            const uint32_t pofs = (c & 1) ? AT_PS1 : AT_PS0;
            const int nb = wc * 64 + g;
            const int rb = wr * 32 + g;
#pragma unroll
            for (int k0 = 0; k0 < 32; k0 += 8) {
                uint32_t bf[8][2];
                const int zr0 = zofs + (k0 + tq) * 264 + nb;
#pragma unroll
                for (int nt = 0; nt < 8; nt++) {
                    bf[nt][0] = smu[zr0 + nt * 8];
                    bf[nt][1] = smu[zr0 + 4 * 264 + nt * 8];
                }
#pragma unroll
                for (int mt = 0; mt < 2; mt++) {
                    int ab = pofs + (rb + mt * 16) * 36 + k0 + tq;
                    uint32_t a0 = smu[ab];
                    uint32_t a1 = smu[ab + 8 * 36];
                    uint32_t a2 = smu[ab + 4];
                    uint32_t a3 = smu[ab + 8 * 36 + 4];
#pragma unroll
                    for (int nt = 0; nt < 8; nt++)
                        mma_tf32(acc[mt][nt], a0, a1, a2, a3, bf[nt][0], bf[nt][1]);
                }
            }
        }
    }

    // ---- epilogue: ELU + store (proven)
#pragma unroll
    for (int mt = 0; mt < 2; mt++) {
        int row0 = i0 + wr * 32 + mt * 16 + g;
        float* o0 = out + (((size_t)b << 10) + row0) * D_ + wc * 64 + 2 * tq;
        float* o1 = o0 + 8 * D_;
#pragma unroll
        for (int nt = 0; nt < 8; nt++) {
            float v0 = acc[mt][nt][0], v1 = acc[mt][nt][1];
            float v2 = acc[mt][nt][2], v3 = acc[mt][nt][3];
            float2 r0, r1;
            r0.x = (v0 > 0.f) ? v0 : expm1f(v0);
            r0.y = (v1 > 0.f) ? v1 : expm1f(v1);
            r1.x = (v2 > 0.f) ? v2 : expm1f(v2);
            r1.y = (v3 > 0.f) ? v3 : expm1f(v3);
            *(float2*)(o0 + nt * 8) = r0;
            *(float2*)(o1 + nt * 8) = r1;
        }
    }
}

// ---------------------------------------------------------------------------
extern "C" void kernel_launch(void* const* d_in, const int* in_sizes, int n_in,
                              void* d_out, int out_size) {
    const float* h    = (const float*)d_in[0];
    const int*   adj  = (const int*)d_in[1];
    const float* W    = (const float*)d_in[2];
    const float* bias = (const float*)d_in[3];
    const float* a    = (const float*)d_in[4];
    float* out = (float*)d_out;
    (void)in_sizes; (void)n_in; (void)out_size;

    cudaFuncSetAttribute(k_attn10, cudaFuncAttributeMaxDynamicSharedMemorySize,
                         AT_SMF * sizeof(float));

    float* p_ptr;
    cudaGetSymbolAddress((void**)&p_ptr, g_p);

    k_zgemm7<<<dim3(2, 256), 256>>>(h, W, bias, a);
    k_combine2<<<128, 256>>>();
    k_maskstat4<<<(B_ * N_) / 8, 256>>>(adj);
    k_attn10<<<dim3(16, 32), 256, AT_SMF * sizeof(float)>>>(p_ptr, out);
}